// round 3
// baseline (speedup 1.0000x reference)
#include <cuda_runtime.h>
#include <math.h>

// Problem dims
#define IMG_W 512
#define IMG_H 512
#define NPLANE 48                     // 16 batch * 3 channels
#define PLANE (IMG_W * IMG_H)         // 262144
#define TOT (NPLANE * PLANE)          // 12582912

#define T_V 32                        // output rows per thread in vertical pass
#define EPSF 1e-8f

// ---------------------------------------------------------------------------
// Scratch (allocation-free rule: __device__ globals)
// ---------------------------------------------------------------------------
__device__ float g_h0[TOT];           // horizontal blur sigma=2
__device__ float g_h1[TOT];           // horizontal blur sigma=4
__device__ float g_h2[TOT];           // horizontal blur sigma=8
__device__ float g_refl[TOT];         // reflectance (log - illum)
__device__ float2 g_part[NPLANE * 32];// per-block (sum, sumsq) partials
__device__ float2 g_stats[NPLANE];    // per-plane (mean, 1/(std+eps))

// ---------------------------------------------------------------------------
// Compile-time Gaussian coefficients (match reference to ~1e-7 relative).
// Reference: g2d[i][j] = exp(-(ri^2+rj^2)/(2s^2)) / S^2  with S = sum exp(-r^2/(2s^2))
// Separable 1D factor: c[i] = exp(-ri^2/(2s^2)) / S.
// ---------------------------------------------------------------------------
__host__ __device__ constexpr double cexp(double x) {
    double t = 1.0, s = 1.0;
    for (int k = 1; k < 60; k++) { t *= x / (double)k; s += t; }
    return s;
}

template <int R>
struct Gauss {
    float c[2 * R + 1];
    __host__ __device__ constexpr Gauss(double sigma, double wmul) : c{} {
        double S = 0.0;
        for (int i = -R; i <= R; i++)
            S += cexp(-(double)(i * i) / (2.0 * sigma * sigma));
        for (int i = -R; i <= R; i++)
            c[i + R] = (float)(wmul * cexp(-(double)(i * i) / (2.0 * sigma * sigma)) / S);
    }
};

// ---------------------------------------------------------------------------
// Pass 1: horizontal blurs (3 at once) of log(rgb + eps), zero-padded.
// One block per (plane, row). 128 threads x 4 pixels.
// ---------------------------------------------------------------------------
__global__ __launch_bounds__(128) void pass_h(const float* __restrict__ rgb) {
    constexpr Gauss<6>  C0(2.0, 1.0);
    constexpr Gauss<12> C1(4.0, 1.0);
    constexpr Gauss<24> C2(8.0, 1.0);

    __shared__ __align__(16) float srow[IMG_W + 48];

    const int plane = blockIdx.y;
    const int y = blockIdx.x;
    const int tid = threadIdx.x;
    const float* row = rgb + (size_t)plane * PLANE + (size_t)y * IMG_W;

    // Load row with 24-wide zero halo; log computed once here.
    for (int i = tid; i < IMG_W + 48; i += 128) {
        int x = i - 24;
        float v = 0.0f;
        if (x >= 0 && x < IMG_W) v = logf(row[x] + EPSF);
        srow[i] = v;
    }
    __syncthreads();

    const int x0 = tid * 4;
    float win[52];
    const float4* s4 = reinterpret_cast<const float4*>(srow + x0);
#pragma unroll
    for (int j = 0; j < 13; j++) {
        float4 v = s4[j];
        win[4 * j + 0] = v.x; win[4 * j + 1] = v.y;
        win[4 * j + 2] = v.z; win[4 * j + 3] = v.w;
    }

    float a0[4], a1[4], a2[4];
#pragma unroll
    for (int p = 0; p < 4; p++) {
        float s2 = 0.0f;
#pragma unroll
        for (int j = 0; j < 49; j++) s2 = fmaf(win[p + j], C2.c[j], s2);
        a2[p] = s2;
        float s1 = 0.0f;
#pragma unroll
        for (int j = 0; j < 25; j++) s1 = fmaf(win[p + 12 + j], C1.c[j], s1);
        a1[p] = s1;
        float s0 = 0.0f;
#pragma unroll
        for (int j = 0; j < 13; j++) s0 = fmaf(win[p + 18 + j], C0.c[j], s0);
        a0[p] = s0;
    }

    const size_t o = (size_t)plane * PLANE + (size_t)y * IMG_W + x0;
    *reinterpret_cast<float4*>(&g_h0[o]) = make_float4(a0[0], a0[1], a0[2], a0[3]);
    *reinterpret_cast<float4*>(&g_h1[o]) = make_float4(a1[0], a1[1], a1[2], a1[3]);
    *reinterpret_cast<float4*>(&g_h2[o]) = make_float4(a2[0], a2[1], a2[2], a2[3]);
}

// ---------------------------------------------------------------------------
// Pass 2: vertical blurs + weighted combine + reflectance + stats partials.
// Register sliding-window: thread = one column, T_V output rows.
// ---------------------------------------------------------------------------
template <int R, bool FIRST>
__device__ __forceinline__ void vconv(const float* __restrict__ base, int x, int y0,
                                      const Gauss<R>& g, float (&acc)[T_V]) {
    float w[2 * R + 1];
#pragma unroll
    for (int j = 0; j < 2 * R; j++) {
        int y = y0 - R + j;
        w[j] = (y >= 0 && y < IMG_H) ? base[y * IMG_W + x] : 0.0f;
    }
#pragma unroll
    for (int t = 0; t < T_V; t++) {
        int y = y0 + t + R;
        w[2 * R] = (y < IMG_H) ? base[y * IMG_W + x] : 0.0f;
        float s = 0.0f;
#pragma unroll
        for (int j = 0; j < 2 * R + 1; j++) s = fmaf(w[j], g.c[j], s);
        if (FIRST) acc[t] = s; else acc[t] += s;
#pragma unroll
        for (int j = 0; j < 2 * R; j++) w[j] = w[j + 1];
    }
}

__global__ __launch_bounds__(256) void pass_v(const float* __restrict__ rgb) {
    // Weights [1, .75, .5]/2.25 folded into vertical coefficients.
    constexpr Gauss<6>  C0(2.0, 1.0 / 2.25);
    constexpr Gauss<12> C1(4.0, 0.75 / 2.25);
    constexpr Gauss<24> C2(8.0, 0.5 / 2.25);

    const int x = blockIdx.x * 256 + threadIdx.x;
    const int y0 = blockIdx.y * T_V;
    const int plane = blockIdx.z;
    const size_t po = (size_t)plane * PLANE;

    float acc[T_V];
    vconv<24, true >(g_h2 + po, x, y0, C2, acc);
    vconv<12, false>(g_h1 + po, x, y0, C1, acc);
    vconv<6,  false>(g_h0 + po, x, y0, C0, acc);

    float psum = 0.0f, psq = 0.0f;
#pragma unroll
    for (int t = 0; t < T_V; t++) {
        const size_t idx = po + (size_t)(y0 + t) * IMG_W + x;
        float lg = logf(rgb[idx] + EPSF);
        float r = lg - acc[t];
        g_refl[idx] = r;
        psum += r;
        psq = fmaf(r, r, psq);
    }

    // Deterministic block reduction (no float atomics).
#pragma unroll
    for (int off = 16; off; off >>= 1) {
        psum += __shfl_down_sync(0xffffffffu, psum, off);
        psq  += __shfl_down_sync(0xffffffffu, psq, off);
    }
    __shared__ float ssum[8], ssq[8];
    const int lane = threadIdx.x & 31;
    const int wid = threadIdx.x >> 5;
    if (lane == 0) { ssum[wid] = psum; ssq[wid] = psq; }
    __syncthreads();
    if (threadIdx.x == 0) {
        float a = 0.0f, b = 0.0f;
#pragma unroll
        for (int i = 0; i < 8; i++) { a += ssum[i]; b += ssq[i]; }
        // partial slot: plane*32 + by*2 + bx   (16 y-tiles x 2 x-tiles)
        g_part[plane * 32 + blockIdx.y * 2 + blockIdx.x] = make_float2(a, b);
    }
}

// ---------------------------------------------------------------------------
// Pass 3: fold 32 partials per plane -> mean, 1/(std+eps).  ddof = 1.
// ---------------------------------------------------------------------------
__global__ void reduce_stats() {
    const int plane = blockIdx.x;
    const int lane = threadIdx.x;
    float2 p = g_part[plane * 32 + lane];
    float s = p.x, q = p.y;
#pragma unroll
    for (int off = 16; off; off >>= 1) {
        s += __shfl_down_sync(0xffffffffu, s, off);
        q += __shfl_down_sync(0xffffffffu, q, off);
    }
    if (lane == 0) {
        const float N = (float)PLANE;
        float mean = s / N;
        float var = (q - s * s / N) / (N - 1.0f);
        float stdv = sqrtf(var);
        g_stats[plane] = make_float2(mean, 1.0f / (stdv + EPSF));
    }
}

// ---------------------------------------------------------------------------
// Pass 4: normalize, exp, clip to [0,1].
// ---------------------------------------------------------------------------
__global__ __launch_bounds__(256) void pass_f(float* __restrict__ out) {
    const unsigned i = (blockIdx.x * 256u + threadIdx.x) * 4u;
    const unsigned plane = i >> 18;   // / PLANE (2^18)
    const float2 st = g_stats[plane];
    const float mean = st.x, inv = st.y;

    float4 r = *reinterpret_cast<const float4*>(&g_refl[i]);
    float4 o;
    o.x = fminf(expf((r.x - mean) * inv), 1.0f);
    o.y = fminf(expf((r.y - mean) * inv), 1.0f);
    o.z = fminf(expf((r.z - mean) * inv), 1.0f);
    o.w = fminf(expf((r.w - mean) * inv), 1.0f);
    *reinterpret_cast<float4*>(&out[i]) = o;
}

// ---------------------------------------------------------------------------
// Launch
// ---------------------------------------------------------------------------
extern "C" void kernel_launch(void* const* d_in, const int* in_sizes, int n_in,
                              void* d_out, int out_size) {
    const float* rgb = (const float*)d_in[0];   // (16,3,512,512) f32
    float* out = (float*)d_out;                 // same shape, f32

    dim3 gh(IMG_H, NPLANE);                     // one block per row per plane
    pass_h<<<gh, 128>>>(rgb);

    dim3 gv(IMG_W / 256, IMG_H / T_V, NPLANE);  // (2, 16, 48)
    pass_v<<<gv, 256>>>(rgb);

    reduce_stats<<<NPLANE, 32>>>();

    pass_f<<<TOT / (4 * 256), 256>>>(out);
}